// round 1
// baseline (speedup 1.0000x reference)
#include <cuda_runtime.h>
#include <math.h>

// TimeLSTM: B=256, S=512, D=64, H=128
// Inputs (metadata order): x[B*S*D], TimeDiff[B*S], weights_x[D*640],
//   weights_h[128*384], weights_t1[128], weights_t[256], bias[640]
// Output: hidden_seq[B*S*H] ++ h_T[B*H] ++ c_T[B*H]  (float32)

#define BB 256
#define SS 512
#define DD 64
#define HH 128
#define GG (5*HH)   // 640

// Scratch: pre-activations [B][S][640]
__device__ float g_pre[(size_t)BB * SS * GG];

__device__ __forceinline__ float sigm(float x) {
    return 1.0f / (1.0f + __expf(-x));
}

// ---------------------------------------------------------------------------
// Kernel A: pre[b][s][0:640] = x_row @ Wx + bias + time-gate extras
//   cols [  0,128): + 0
//   cols [128,256): + tanh(td * min(wt1, 0))
//   cols [256,384): + tanh(td * wt[0:128])
//   cols [384,512): + 0
//   cols [512,640): + td * wt[128:256]
// Block: 160 threads (each owns 4 consecutive output cols), RA rows per block.
// ---------------------------------------------------------------------------
#define RA 16
__global__ __launch_bounds__(160) void pre_kernel(
    const float* __restrict__ x, const float* __restrict__ td,
    const float* __restrict__ Wx, const float* __restrict__ wt1,
    const float* __restrict__ wt, const float* __restrict__ bias)
{
    __shared__ float xs[RA][DD];
    __shared__ float tds[RA];
    const int tid = threadIdx.x;
    const size_t row0 = (size_t)blockIdx.x * RA;

    for (int i = tid; i < RA * DD; i += 160)
        xs[i >> 6][i & 63] = x[row0 * DD + i];
    if (tid < RA) tds[tid] = td[row0 + tid];
    __syncthreads();

    float acc[RA][4];
    #pragma unroll
    for (int r = 0; r < RA; r++) { acc[r][0]=0.f; acc[r][1]=0.f; acc[r][2]=0.f; acc[r][3]=0.f; }

    const float4* __restrict__ W4 = (const float4*)Wx;
    #pragma unroll 4
    for (int k = 0; k < DD; k++) {
        float4 w = W4[k * (GG/4) + tid];
        #pragma unroll
        for (int r = 0; r < RA; r++) {
            float xv = xs[r][k];
            acc[r][0] = fmaf(xv, w.x, acc[r][0]);
            acc[r][1] = fmaf(xv, w.y, acc[r][1]);
            acc[r][2] = fmaf(xv, w.z, acc[r][2]);
            acc[r][3] = fmaf(xv, w.w, acc[r][3]);
        }
    }

    const int c0 = tid * 4;
    const int mode = c0 >> 7;   // 0..4, all 4 cols of a thread share one gate region
    float4 bv = ((const float4*)bias)[tid];

    float4 wv = make_float4(0.f, 0.f, 0.f, 0.f);
    if (mode == 1) {
        wv.x = fminf(wt1[c0 - 128], 0.f);
        wv.y = fminf(wt1[c0 - 127], 0.f);
        wv.z = fminf(wt1[c0 - 126], 0.f);
        wv.w = fminf(wt1[c0 - 125], 0.f);
    } else if (mode == 2) {
        wv = ((const float4*)wt)[tid - 64];   // wt[c0-256 ...]
    } else if (mode == 4) {
        wv = ((const float4*)wt)[tid - 96];   // wt[c0-384 ...] = wt[128 + (c0-512)]
    }

    #pragma unroll 4
    for (int r = 0; r < RA; r++) {
        float t = tds[r];
        float4 ex;
        if (mode == 1 || mode == 2) {
            ex.x = tanhf(t * wv.x); ex.y = tanhf(t * wv.y);
            ex.z = tanhf(t * wv.z); ex.w = tanhf(t * wv.w);
        } else if (mode == 4) {
            ex.x = t * wv.x; ex.y = t * wv.y; ex.z = t * wv.z; ex.w = t * wv.w;
        } else {
            ex = make_float4(0.f, 0.f, 0.f, 0.f);
        }
        float4 o;
        o.x = acc[r][0] + bv.x + ex.x;
        o.y = acc[r][1] + bv.y + ex.y;
        o.z = acc[r][2] + bv.z + ex.z;
        o.w = acc[r][3] + bv.w + ex.w;
        ((float4*)(g_pre + (row0 + r) * GG))[tid] = o;
    }
}

// ---------------------------------------------------------------------------
// Kernel B: sequential scan. One block per batch row. 384 threads:
// thread j owns column j of Wh (128x384, cols [0:128)=i, [128:256)=c, [256:384)=o)
// in registers. h lives in SMEM; pre[s+1] is register-prefetched during the
// step-s matvec (double-buffered into SMEM).
// ---------------------------------------------------------------------------
__global__ __launch_bounds__(384, 2) void rec_kernel(
    const float* __restrict__ Wh, float* __restrict__ out)
{
    __shared__ float h_smem[HH];
    __shared__ float a_smem[3 * HH];
    __shared__ float pre_buf[2][GG];

    const int tid = threadIdx.x;
    const int b   = blockIdx.x;
    const float* __restrict__ pre_src = g_pre + (size_t)b * SS * GG;

    // W column -> registers (coalesced: 384 consecutive floats per k)
    float w[HH];
    #pragma unroll
    for (int k = 0; k < HH; k++) w[k] = Wh[k * (3 * HH) + tid];

    if (tid < HH) h_smem[tid] = 0.f;
    if (tid < GG / 4)
        ((float4*)pre_buf[0])[tid] = ((const float4*)pre_src)[tid];
    __syncthreads();

    float c_t = 0.f, h_keep = 0.f;
    float* __restrict__ hseq = out;
    float* __restrict__ hT = out + (size_t)BB * SS * HH;
    float* __restrict__ cT = hT + (size_t)BB * HH;

    for (int s = 0; s < SS; s++) {
        // Prefetch pre[s+1] into registers (latency hidden behind matvec)
        float4 pf;
        const bool do_pf = (tid < GG / 4) && (s + 1 < SS);
        if (do_pf)
            pf = ((const float4*)(pre_src + (size_t)(s + 1) * GG))[tid];

        // Matvec: a_j = dot(h, Wh[:, j]); 4 independent accumulator chains
        float a0 = 0.f, a1 = 0.f, a2 = 0.f, a3 = 0.f;
        const float4* h4 = (const float4*)h_smem;
        #pragma unroll
        for (int k4 = 0; k4 < HH / 4; k4++) {
            float4 hv = h4[k4];          // broadcast across warp
            a0 = fmaf(hv.x, w[4*k4+0], a0);
            a1 = fmaf(hv.y, w[4*k4+1], a1);
            a2 = fmaf(hv.z, w[4*k4+2], a2);
            a3 = fmaf(hv.w, w[4*k4+3], a3);
        }
        a_smem[tid] = (a0 + a1) + (a2 + a3);
        if (do_pf)
            ((float4*)pre_buf[(s + 1) & 1])[tid] = pf;
        __syncthreads();

        if (tid < HH) {
            const float* __restrict__ p = pre_buf[s & 1];
            float ai  = p[tid]          + a_smem[tid];
            float pt1 = p[HH + tid];
            float pt2 = p[2 * HH + tid];
            float ac  = p[3 * HH + tid] + a_smem[HH + tid];
            float ao  = p[4 * HH + tid] + a_smem[2 * HH + tid];

            float i_t = sigm(ai);
            float t1  = sigm(pt1);
            float t2  = sigm(pt2);
            float cw  = tanhf(ac);
            float o_t = sigm(ao);

            float it1  = i_t * t1;
            float ctil = sigm((1.f - it1) * c_t + it1 * cw);
            c_t        = sigm((1.f - i_t) * c_t + i_t * t2 * cw);
            float hn   = o_t + tanhf(ctil);

            h_smem[tid] = hn;
            h_keep = hn;
            hseq[((size_t)b * SS + s) * HH + tid] = hn;
        }
        __syncthreads();
    }

    if (tid < HH) {
        hT[(size_t)b * HH + tid] = h_keep;
        cT[(size_t)b * HH + tid] = c_t;
    }
}

extern "C" void kernel_launch(void* const* d_in, const int* in_sizes, int n_in,
                              void* d_out, int out_size) {
    const float* x   = (const float*)d_in[0];
    const float* td  = (const float*)d_in[1];
    const float* Wx  = (const float*)d_in[2];
    const float* Wh  = (const float*)d_in[3];
    const float* wt1 = (const float*)d_in[4];
    const float* wt  = (const float*)d_in[5];
    const float* bias= (const float*)d_in[6];
    float* out = (float*)d_out;

    pre_kernel<<<(BB * SS) / RA, 160>>>(x, td, Wx, wt1, wt, bias);
    rec_kernel<<<BB, 384>>>(Wh, out);
}

// round 2
// speedup vs baseline: 1.7370x; 1.7370x over previous
#include <cuda_runtime.h>
#include <math.h>

// TimeLSTM: B=256, S=512, D=64, H=128
#define BB 256
#define SS 512
#define DD 64
#define HH 128
#define GG (5*HH)   // 640

__device__ float g_pre[(size_t)BB * SS * GG];

typedef unsigned long long ull;

__device__ __forceinline__ float sigm(float x) { return 1.0f / (1.0f + __expf(-x)); }
__device__ __forceinline__ ull pack2(float lo, float hi) {
    return ((ull)__float_as_uint(hi) << 32) | (ull)__float_as_uint(lo);
}
__device__ __forceinline__ float lo2(ull v) { return __uint_as_float((unsigned)v); }
__device__ __forceinline__ float hi2(ull v) { return __uint_as_float((unsigned)(v >> 32)); }

#define FMA2(d,a,b,c) asm("fma.rn.f32x2 %0, %1, %2, %3;" : "=l"(d) : "l"(a), "l"(b), "l"(c))

__device__ __forceinline__ void cp_async16(void* smem, const void* gmem) {
    unsigned saddr = (unsigned)__cvta_generic_to_shared(smem);
    asm volatile("cp.async.ca.shared.global [%0], [%1], 16;" :: "r"(saddr), "l"(gmem));
}
#define CP_COMMIT() asm volatile("cp.async.commit_group;")
#define CP_WAIT1()  asm volatile("cp.async.wait_group 1;")

// ---------------------------------------------------------------------------
// Kernel A: pre-activations (unchanged from R1 — passed, not dominant)
// ---------------------------------------------------------------------------
#define RA 16
__global__ __launch_bounds__(160) void pre_kernel(
    const float* __restrict__ x, const float* __restrict__ td,
    const float* __restrict__ Wx, const float* __restrict__ wt1,
    const float* __restrict__ wt, const float* __restrict__ bias)
{
    __shared__ float xs[RA][DD];
    __shared__ float tds[RA];
    const int tid = threadIdx.x;
    const size_t row0 = (size_t)blockIdx.x * RA;

    for (int i = tid; i < RA * DD; i += 160)
        xs[i >> 6][i & 63] = x[row0 * DD + i];
    if (tid < RA) tds[tid] = td[row0 + tid];
    __syncthreads();

    float acc[RA][4];
    #pragma unroll
    for (int r = 0; r < RA; r++) { acc[r][0]=0.f; acc[r][1]=0.f; acc[r][2]=0.f; acc[r][3]=0.f; }

    const float4* __restrict__ W4 = (const float4*)Wx;
    #pragma unroll 4
    for (int k = 0; k < DD; k++) {
        float4 w = W4[k * (GG/4) + tid];
        #pragma unroll
        for (int r = 0; r < RA; r++) {
            float xv = xs[r][k];
            acc[r][0] = fmaf(xv, w.x, acc[r][0]);
            acc[r][1] = fmaf(xv, w.y, acc[r][1]);
            acc[r][2] = fmaf(xv, w.z, acc[r][2]);
            acc[r][3] = fmaf(xv, w.w, acc[r][3]);
        }
    }

    const int c0 = tid * 4;
    const int mode = c0 >> 7;
    float4 bv = ((const float4*)bias)[tid];

    float4 wv = make_float4(0.f, 0.f, 0.f, 0.f);
    if (mode == 1) {
        wv.x = fminf(wt1[c0 - 128], 0.f);
        wv.y = fminf(wt1[c0 - 127], 0.f);
        wv.z = fminf(wt1[c0 - 126], 0.f);
        wv.w = fminf(wt1[c0 - 125], 0.f);
    } else if (mode == 2) {
        wv = ((const float4*)wt)[tid - 64];
    } else if (mode == 4) {
        wv = ((const float4*)wt)[tid - 96];
    }

    #pragma unroll 4
    for (int r = 0; r < RA; r++) {
        float t = tds[r];
        float4 ex;
        if (mode == 1 || mode == 2) {
            ex.x = tanhf(t * wv.x); ex.y = tanhf(t * wv.y);
            ex.z = tanhf(t * wv.z); ex.w = tanhf(t * wv.w);
        } else if (mode == 4) {
            ex.x = t * wv.x; ex.y = t * wv.y; ex.z = t * wv.z; ex.w = t * wv.w;
        } else {
            ex = make_float4(0.f, 0.f, 0.f, 0.f);
        }
        float4 o;
        o.x = acc[r][0] + bv.x + ex.x;
        o.y = acc[r][1] + bv.y + ex.y;
        o.z = acc[r][2] + bv.z + ex.z;
        o.w = acc[r][3] + bv.w + ex.w;
        ((float4*)(g_pre + (row0 + r) * GG))[tid] = o;
    }
}

// ---------------------------------------------------------------------------
// Kernel B: sequential scan. 128 blocks x 384 threads; each block owns TWO
// batch rows. Thread tid holds Wh column tid as 64 packed f32x2 pairs in
// registers (128 regs; launch_bounds(384,1) -> no spill). h lives in SMEM
// (LDS.128 broadcast); pre[s+1] arrives via cp.async double buffer.
// ---------------------------------------------------------------------------
__global__ __launch_bounds__(384, 1) void rec_kernel(
    const float* __restrict__ Wh, float* __restrict__ out)
{
    __shared__ __align__(16) float h_smem[2][HH];
    __shared__ float a_smem[2][3 * HH];
    __shared__ __align__(16) float pre_buf[2][2][GG];

    const int tid = threadIdx.x;
    const int b0 = blockIdx.x * 2;

    // Pack Wh column `tid` into 64 f32x2 pairs (coalesced loads per k)
    ull w[HH / 2];
    #pragma unroll
    for (int i = 0; i < HH / 2; i++)
        w[i] = pack2(Wh[(2 * i) * (3 * HH) + tid],
                     Wh[(2 * i + 1) * (3 * HH) + tid]);

    if (tid < 2 * HH) h_smem[tid >> 7][tid & 127] = 0.f;

    // preload pre[s=0] for both rows
    if (tid < 320) {
        int r = tid / 160, i = tid % 160;
        cp_async16(&pre_buf[0][r][i * 4],
                   g_pre + ((size_t)(b0 + r) * SS) * GG + i * 4);
    }
    CP_COMMIT();
    __syncthreads();

    float c_t = 0.f, h_keep = 0.f;
    float* __restrict__ hseq = out;
    float* __restrict__ hT = out + (size_t)BB * SS * HH;
    float* __restrict__ cT = hT + (size_t)BB * HH;

    for (int s = 0; s < SS; s++) {
        // prefetch pre[s+1] into the other buffer
        if (tid < 320 && s + 1 < SS) {
            int r = tid / 160, i = tid % 160;
            cp_async16(&pre_buf[(s + 1) & 1][r][i * 4],
                       g_pre + ((size_t)(b0 + r) * SS + (s + 1)) * GG + i * 4);
        }
        CP_COMMIT();

        // matvec for both rows, packed f32x2, 4 independent chains
        ull a00 = 0, a01 = 0, a10 = 0, a11 = 0;
        const ulonglong2* h0 = (const ulonglong2*)h_smem[0];
        const ulonglong2* h1 = (const ulonglong2*)h_smem[1];
        #pragma unroll
        for (int k4 = 0; k4 < HH / 4; k4++) {
            ulonglong2 v0 = h0[k4];
            ulonglong2 v1 = h1[k4];
            FMA2(a00, v0.x, w[2 * k4    ], a00);
            FMA2(a01, v0.y, w[2 * k4 + 1], a01);
            FMA2(a10, v1.x, w[2 * k4    ], a10);
            FMA2(a11, v1.y, w[2 * k4 + 1], a11);
        }
        a_smem[0][tid] = (lo2(a00) + hi2(a00)) + (lo2(a01) + hi2(a01));
        a_smem[1][tid] = (lo2(a10) + hi2(a10)) + (lo2(a11) + hi2(a11));

        CP_WAIT1();          // pre[s] resident (pre[s+1] may still be in flight)
        __syncthreads();

        if (tid < 2 * HH) {
            const int r = tid >> 7, j = tid & 127;
            const float* __restrict__ p = pre_buf[s & 1][r];
            float ai  = p[j]           + a_smem[r][j];
            float pt1 = p[HH + j];
            float pt2 = p[2 * HH + j];
            float ac  = p[3 * HH + j]  + a_smem[r][HH + j];
            float ao  = p[4 * HH + j]  + a_smem[r][2 * HH + j];

            float i_t = sigm(ai);
            float t1  = sigm(pt1);
            float t2  = sigm(pt2);
            float cw  = tanhf(ac);
            float o_t = sigm(ao);

            float it1  = i_t * t1;
            float ctil = sigm((1.f - it1) * c_t + it1 * cw);
            c_t        = sigm((1.f - i_t) * c_t + i_t * t2 * cw);
            float hn   = o_t + tanhf(ctil);

            h_smem[r][j] = hn;
            h_keep = hn;
            hseq[((size_t)(b0 + r) * SS + s) * HH + j] = hn;
        }
        __syncthreads();
    }

    if (tid < 2 * HH) {
        const int r = tid >> 7, j = tid & 127;
        hT[(size_t)(b0 + r) * HH + j] = h_keep;
        cT[(size_t)(b0 + r) * HH + j] = c_t;
    }
}

extern "C" void kernel_launch(void* const* d_in, const int* in_sizes, int n_in,
                              void* d_out, int out_size) {
    const float* x    = (const float*)d_in[0];
    const float* td   = (const float*)d_in[1];
    const float* Wx   = (const float*)d_in[2];
    const float* Wh   = (const float*)d_in[3];
    const float* wt1  = (const float*)d_in[4];
    const float* wt   = (const float*)d_in[5];
    const float* bias = (const float*)d_in[6];
    float* out = (float*)d_out;

    pre_kernel<<<(BB * SS) / RA, 160>>>(x, td, Wx, wt1, wt, bias);
    rec_kernel<<<BB / 2, 384>>>(Wh, out);
}

// round 3
// speedup vs baseline: 1.7528x; 1.0091x over previous
#include <cuda_runtime.h>
#include <math.h>

// TimeLSTM: B=256, S=512, D=64, H=128
#define BB 256
#define SS 512
#define DD 64
#define HH 128
#define GG (5*HH)   // 640

__device__ float g_pre[(size_t)BB * SS * GG];

typedef unsigned long long ull;

__device__ __forceinline__ float sigm(float x) { return 1.0f / (1.0f + __expf(-x)); }
// exact-ish tanh via sigmoid identity (avoids slow tanhf library path)
__device__ __forceinline__ float tanh_fast(float x) {
    float s = 1.0f / (1.0f + __expf(-2.0f * x));
    return fmaf(2.0f, s, -1.0f);
}
__device__ __forceinline__ ull pack2(float lo, float hi) {
    return ((ull)__float_as_uint(hi) << 32) | (ull)__float_as_uint(lo);
}
__device__ __forceinline__ float lo2(ull v) { return __uint_as_float((unsigned)v); }
__device__ __forceinline__ float hi2(ull v) { return __uint_as_float((unsigned)(v >> 32)); }

#define FMA2(d,a,b,c) asm("fma.rn.f32x2 %0, %1, %2, %3;" : "=l"(d) : "l"(a), "l"(b), "l"(c))

__device__ __forceinline__ void cp_async16(void* smem, const void* gmem) {
    unsigned saddr = (unsigned)__cvta_generic_to_shared(smem);
    asm volatile("cp.async.ca.shared.global [%0], [%1], 16;" :: "r"(saddr), "l"(gmem));
}
#define CP_COMMIT() asm volatile("cp.async.commit_group;")
#define CP_WAIT1()  asm volatile("cp.async.wait_group 1;")

// ---------------------------------------------------------------------------
// Kernel A: pre-activations. f32x2 everywhere; tanh via sigm identity.
// ---------------------------------------------------------------------------
#define RA 16
__global__ __launch_bounds__(160) void pre_kernel(
    const float* __restrict__ x, const float* __restrict__ td,
    const float* __restrict__ Wx, const float* __restrict__ wt1,
    const float* __restrict__ wt, const float* __restrict__ bias)
{
    __shared__ __align__(16) ull xs2[RA][DD];   // (x,x) duplicated pairs
    __shared__ float tds[RA];
    const int tid = threadIdx.x;
    const size_t row0 = (size_t)blockIdx.x * RA;

    for (int i = tid; i < RA * DD; i += 160) {
        float v = x[row0 * DD + i];
        xs2[i >> 6][i & 63] = pack2(v, v);
    }
    if (tid < RA) tds[tid] = td[row0 + tid];
    __syncthreads();

    // acc[r][0] = cols (c0,c1), acc[r][1] = cols (c2,c3)
    ull acc[RA][2];
    #pragma unroll
    for (int r = 0; r < RA; r++) { acc[r][0] = 0; acc[r][1] = 0; }

    const ulonglong2* __restrict__ W2 = (const ulonglong2*)Wx;
    #pragma unroll 4
    for (int k = 0; k < DD; k++) {
        ulonglong2 w = W2[k * (GG/4) + tid];   // (c0,c1),(c2,c3)
        #pragma unroll
        for (int r = 0; r < RA; r++) {
            ull xx = xs2[r][k];
            FMA2(acc[r][0], xx, w.x, acc[r][0]);
            FMA2(acc[r][1], xx, w.y, acc[r][1]);
        }
    }

    const int c0 = tid * 4;
    const int mode = c0 >> 7;
    float4 bv = ((const float4*)bias)[tid];

    float4 wv = make_float4(0.f, 0.f, 0.f, 0.f);
    if (mode == 1) {
        wv.x = fminf(wt1[c0 - 128], 0.f);
        wv.y = fminf(wt1[c0 - 127], 0.f);
        wv.z = fminf(wt1[c0 - 126], 0.f);
        wv.w = fminf(wt1[c0 - 125], 0.f);
    } else if (mode == 2) {
        wv = ((const float4*)wt)[tid - 64];
    } else if (mode == 4) {
        wv = ((const float4*)wt)[tid - 96];
    }

    #pragma unroll 4
    for (int r = 0; r < RA; r++) {
        float t = tds[r];
        float4 ex;
        if (mode == 1 || mode == 2) {
            ex.x = tanh_fast(t * wv.x); ex.y = tanh_fast(t * wv.y);
            ex.z = tanh_fast(t * wv.z); ex.w = tanh_fast(t * wv.w);
        } else if (mode == 4) {
            ex.x = t * wv.x; ex.y = t * wv.y; ex.z = t * wv.z; ex.w = t * wv.w;
        } else {
            ex = make_float4(0.f, 0.f, 0.f, 0.f);
        }
        float4 o;
        o.x = lo2(acc[r][0]) + bv.x + ex.x;
        o.y = hi2(acc[r][0]) + bv.y + ex.y;
        o.z = lo2(acc[r][1]) + bv.z + ex.z;
        o.w = hi2(acc[r][1]) + bv.w + ex.w;
        ((float4*)(g_pre + (row0 + r) * GG))[tid] = o;
    }
}

// ---------------------------------------------------------------------------
// Kernel B: sequential scan. 128 blocks x 768 threads; block owns 2 batch
// rows. Thread (col, khalf) holds Wh[khalf*64 : khalf*64+64, col] as 32
// packed f32x2 regs. k-split halves per-thread registers -> 24 warps/SM.
// Partial dots land in a_part[khalf][row][col]; epilogue (256 thr) sums.
// ---------------------------------------------------------------------------
__global__ __launch_bounds__(768, 1) void rec_kernel(
    const float* __restrict__ Wh, float* __restrict__ out)
{
    __shared__ __align__(16) float h_smem[2][HH];
    __shared__ float a_part[2][2][3 * HH];       // [khalf][row][col]
    __shared__ __align__(16) float pre_buf[2][2][GG];

    const int tid = threadIdx.x;
    const int kh  = (tid >= 384) ? 1 : 0;
    const int col = tid - 384 * kh;
    const int b0  = blockIdx.x * 2;
    const int kbase = kh * 64;

    // 64 weights -> 32 f32x2 pairs (coalesced across col)
    ull w[32];
    #pragma unroll
    for (int i = 0; i < 32; i++)
        w[i] = pack2(Wh[(kbase + 2*i    ) * (3*HH) + col],
                     Wh[(kbase + 2*i + 1) * (3*HH) + col]);

    if (tid < 2 * HH) h_smem[tid >> 7][tid & 127] = 0.f;

    if (tid < 320) {
        int r = tid / 160, i = tid % 160;
        cp_async16(&pre_buf[0][r][i * 4],
                   g_pre + ((size_t)(b0 + r) * SS) * GG + i * 4);
    }
    CP_COMMIT();
    __syncthreads();

    float c_t = 0.f, h_keep = 0.f;
    float* __restrict__ hseq = out;
    float* __restrict__ hT = out + (size_t)BB * SS * HH;
    float* __restrict__ cT = hT + (size_t)BB * HH;

    for (int s = 0; s < SS; s++) {
        if (tid < 320 && s + 1 < SS) {
            int r = tid / 160, i = tid % 160;
            cp_async16(&pre_buf[(s + 1) & 1][r][i * 4],
                       g_pre + ((size_t)(b0 + r) * SS + (s + 1)) * GG + i * 4);
        }
        CP_COMMIT();

        // half-k matvec for both rows
        ull a0 = 0, a1 = 0;
        const ulonglong2* h0 = (const ulonglong2*)(h_smem[0] + kbase);
        const ulonglong2* h1 = (const ulonglong2*)(h_smem[1] + kbase);
        #pragma unroll
        for (int i = 0; i < 16; i++) {
            ulonglong2 v0 = h0[i];
            FMA2(a0, v0.x, w[2*i    ], a0);
            FMA2(a0, v0.y, w[2*i + 1], a0);
            ulonglong2 v1 = h1[i];
            FMA2(a1, v1.x, w[2*i    ], a1);
            FMA2(a1, v1.y, w[2*i + 1], a1);
        }
        a_part[kh][0][col] = lo2(a0) + hi2(a0);
        a_part[kh][1][col] = lo2(a1) + hi2(a1);

        CP_WAIT1();
        __syncthreads();

        if (tid < 2 * HH) {
            const int r = tid >> 7, j = tid & 127;
            const float* __restrict__ p = pre_buf[s & 1][r];
            float ai  = p[j]          + a_part[0][r][j]        + a_part[1][r][j];
            float pt1 = p[HH + j];
            float pt2 = p[2*HH + j];
            float ac  = p[3*HH + j]   + a_part[0][r][HH + j]   + a_part[1][r][HH + j];
            float ao  = p[4*HH + j]   + a_part[0][r][2*HH + j] + a_part[1][r][2*HH + j];

            float i_t = sigm(ai);
            float t1  = sigm(pt1);
            float t2  = sigm(pt2);
            float cw  = tanh_fast(ac);
            float o_t = sigm(ao);

            float it1  = i_t * t1;
            float ctil = sigm((1.f - it1) * c_t + it1 * cw);
            c_t        = sigm((1.f - i_t) * c_t + i_t * t2 * cw);
            float hn   = o_t + tanh_fast(ctil);

            h_smem[r][j] = hn;
            h_keep = hn;
            hseq[((size_t)(b0 + r) * SS + s) * HH + j] = hn;
        }
        __syncthreads();
    }

    if (tid < 2 * HH) {
        const int r = tid >> 7, j = tid & 127;
        hT[(size_t)(b0 + r) * HH + j] = h_keep;
        cT[(size_t)(b0 + r) * HH + j] = c_t;
    }
}

extern "C" void kernel_launch(void* const* d_in, const int* in_sizes, int n_in,
                              void* d_out, int out_size) {
    const float* x    = (const float*)d_in[0];
    const float* td   = (const float*)d_in[1];
    const float* Wx   = (const float*)d_in[2];
    const float* Wh   = (const float*)d_in[3];
    const float* wt1  = (const float*)d_in[4];
    const float* wt   = (const float*)d_in[5];
    const float* bias = (const float*)d_in[6];
    float* out = (float*)d_out;

    pre_kernel<<<(BB * SS) / RA, 160>>>(x, td, Wx, wt1, wt, bias);
    rec_kernel<<<BB / 2, 768>>>(Wh, out);
}